// round 1
// baseline (speedup 1.0000x reference)
#include <cuda_runtime.h>
#include <math.h>

#define NB 1024   // n = H*W
#define DD 512    // d
#define BB 32     // batch

// Scratch (no allocations allowed)
__device__ float g_xf[BB * DD * NB];   // 64 MB, layout [b][c][i] (i contiguous)
__device__ float g_S [ (size_t)BB * NB * NB ]; // 128 MB, [b][i][j]
__device__ float g_u [BB * NB];
__device__ float g_v [BB * NB];

// ---------------------------------------------------------------------------
// Kernel 1: xf[b][c][i] = x[b][c][i] + pos[c][i]
//   pos[c][i]: c<256 -> col_embed[w][c] ; c>=256 -> row_embed[h][c-256]
//   i = h*32 + w
// ---------------------------------------------------------------------------
__global__ void build_xf_kernel(const float* __restrict__ x,
                                const float* __restrict__ rowe,
                                const float* __restrict__ cole,
                                float* __restrict__ xf)
{
    int idx = blockIdx.x * 256 + threadIdx.x;     // [0, BB*DD*NB)
    int i = idx & (NB - 1);
    int c = (idx >> 10) & (DD - 1);
    int h = i >> 5;
    int w = i & 31;
    float p = (c < 256) ? cole[w * 256 + c] : rowe[h * 256 + (c - 256)];
    xf[idx] = x[idx] + p;
}

// ---------------------------------------------------------------------------
// Kernel 2: S[b][i][j] = (1/sqrt(d)) * sum_c xf[b][c][i] * xf[b][c][j]
// Symmetric: only upper-triangular 128x128 block pairs; mirror-write.
// ---------------------------------------------------------------------------
__global__ __launch_bounds__(256) void s_gemm_kernel(const float* __restrict__ xf,
                                                     float* __restrict__ Sg)
{
    const int b = blockIdx.y;
    const float* A  = xf + (size_t)b * DD * NB;
    float*       Sb = Sg + (size_t)b * NB * NB;

    // decode upper-triangular block pair
    int t = blockIdx.x, bi = 0;
    while (t >= 8 - bi) { t -= 8 - bi; ++bi; }
    const int bj = bi + t;
    const int i0 = bi * 128, j0 = bj * 128;

    __shared__ float As[8][132];
    __shared__ float Bs[8][132];

    const int tid = threadIdx.x;
    const int tx = tid & 15, ty = tid >> 4;
    const int lk = tid >> 5;           // 0..7
    const int li = (tid & 31) * 4;     // 0..124

    float acc[8][8];
#pragma unroll
    for (int a = 0; a < 8; ++a)
#pragma unroll
        for (int q = 0; q < 8; ++q) acc[a][q] = 0.f;

    for (int c0 = 0; c0 < DD; c0 += 8) {
        float4 va = *(const float4*)&A[(size_t)(c0 + lk) * NB + i0 + li];
        float4 vb = *(const float4*)&A[(size_t)(c0 + lk) * NB + j0 + li];
        *(float4*)&As[lk][li] = va;
        *(float4*)&Bs[lk][li] = vb;
        __syncthreads();
#pragma unroll
        for (int k = 0; k < 8; ++k) {
            float ra[8], rb[8];
            *(float4*)(ra)     = *(const float4*)&As[k][ty * 4];
            *(float4*)(ra + 4) = *(const float4*)&As[k][64 + ty * 4];
            *(float4*)(rb)     = *(const float4*)&Bs[k][tx * 4];
            *(float4*)(rb + 4) = *(const float4*)&Bs[k][64 + tx * 4];
#pragma unroll
            for (int a = 0; a < 8; ++a)
#pragma unroll
                for (int q = 0; q < 8; ++q)
                    acc[a][q] = fmaf(ra[a], rb[q], acc[a][q]);
        }
        __syncthreads();
    }

    const float scale = 0.044194173824159216f; // 1/sqrt(512)
#pragma unroll
    for (int a = 0; a < 8; ++a)
#pragma unroll
        for (int q = 0; q < 8; ++q) acc[a][q] *= scale;

    // normal tile write: rows = i, cols = j (contiguous)
#pragma unroll
    for (int a = 0; a < 8; ++a) {
        int r = i0 + ((a < 4) ? (ty * 4 + a) : (64 + ty * 4 + a - 4));
        float4 w0 = make_float4(acc[a][0], acc[a][1], acc[a][2], acc[a][3]);
        float4 w1 = make_float4(acc[a][4], acc[a][5], acc[a][6], acc[a][7]);
        *(float4*)&Sb[(size_t)r * NB + j0 + tx * 4]      = w0;
        *(float4*)&Sb[(size_t)r * NB + j0 + 64 + tx * 4] = w1;
    }
    // mirror tile write (rows = j, cols = i)
    if (bi != bj) {
#pragma unroll
        for (int q = 0; q < 8; ++q) {
            int cc = j0 + ((q < 4) ? (tx * 4 + q) : (64 + tx * 4 + q - 4));
            float4 w0 = make_float4(acc[0][q], acc[1][q], acc[2][q], acc[3][q]);
            float4 w1 = make_float4(acc[4][q], acc[5][q], acc[6][q], acc[7][q]);
            *(float4*)&Sb[(size_t)cc * NB + i0 + ty * 4]      = w0;
            *(float4*)&Sb[(size_t)cc * NB + i0 + 64 + ty * 4] = w1;
        }
    }
}

// ---------------------------------------------------------------------------
// Kernel 3: u[b][i] = -log(n) - LSE_j( S[b][i][j] )
// one block (256 thr) per row
// ---------------------------------------------------------------------------
__global__ void row_lse_u_kernel(const float* __restrict__ Sg, float* __restrict__ u)
{
    const int b = blockIdx.y, i = blockIdx.x;
    const float* row = Sg + (size_t)b * NB * NB + (size_t)i * NB;
    const int tid = threadIdx.x;

    float4 v4 = ((const float4*)row)[tid];
    float m = fmaxf(fmaxf(v4.x, v4.y), fmaxf(v4.z, v4.w));
#pragma unroll
    for (int o = 16; o > 0; o >>= 1) m = fmaxf(m, __shfl_xor_sync(~0u, m, o));
    __shared__ float sm[8], ss[8];
    if ((tid & 31) == 0) sm[tid >> 5] = m;
    __syncthreads();
    float mm = sm[0];
#pragma unroll
    for (int k = 1; k < 8; ++k) mm = fmaxf(mm, sm[k]);

    float s = __expf(v4.x - mm) + __expf(v4.y - mm) + __expf(v4.z - mm) + __expf(v4.w - mm);
#pragma unroll
    for (int o = 16; o > 0; o >>= 1) s += __shfl_xor_sync(~0u, s, o);
    if ((tid & 31) == 0) ss[tid >> 5] = s;
    __syncthreads();
    if (tid == 0) {
        float tot = 0.f;
#pragma unroll
        for (int k = 0; k < 8; ++k) tot += ss[k];
        u[b * NB + i] = -logf((float)NB) - (mm + logf(tot));
    }
}

// ---------------------------------------------------------------------------
// Kernel 4: v[b][j] = -log(n) - LSE_i( S[b][i][j] + u[b][i] )
// uses exact symmetry S[i][j] == S[j][i] (guaranteed by mirror writes),
// so read row j coalesced.
// ---------------------------------------------------------------------------
__global__ void col_lse_v_kernel(const float* __restrict__ Sg,
                                 const float* __restrict__ u,
                                 float* __restrict__ v)
{
    const int b = blockIdx.y, j = blockIdx.x;
    const float* row = Sg + (size_t)b * NB * NB + (size_t)j * NB;
    const float* ub  = u + b * NB;
    const int tid = threadIdx.x;

    float4 s4 = ((const float4*)row)[tid];
    float4 u4 = ((const float4*)ub)[tid];
    s4.x += u4.x; s4.y += u4.y; s4.z += u4.z; s4.w += u4.w;

    float m = fmaxf(fmaxf(s4.x, s4.y), fmaxf(s4.z, s4.w));
#pragma unroll
    for (int o = 16; o > 0; o >>= 1) m = fmaxf(m, __shfl_xor_sync(~0u, m, o));
    __shared__ float sm[8], ss[8];
    if ((tid & 31) == 0) sm[tid >> 5] = m;
    __syncthreads();
    float mm = sm[0];
#pragma unroll
    for (int k = 1; k < 8; ++k) mm = fmaxf(mm, sm[k]);

    float s = __expf(s4.x - mm) + __expf(s4.y - mm) + __expf(s4.z - mm) + __expf(s4.w - mm);
#pragma unroll
    for (int o = 16; o > 0; o >>= 1) s += __shfl_xor_sync(~0u, s, o);
    if ((tid & 31) == 0) ss[tid >> 5] = s;
    __syncthreads();
    if (tid == 0) {
        float tot = 0.f;
#pragma unroll
        for (int k = 0; k < 8; ++k) tot += ss[k];
        v[b * NB + j] = -logf((float)NB) - (mm + logf(tot));
    }
}

// ---------------------------------------------------------------------------
// Kernel 5: out[b][c][i] = sum_j xf[b][c][j] * exp(S[b][i][j] + u[i] + v[j])
// GEMM: M=c(128-tile from 512), N=i(128-tile from 1024), K=j(1024)
// attn tile computed on the fly into smem. Output written directly in
// [B][d][H][W] layout (i contiguous -> coalesced).
// ---------------------------------------------------------------------------
__global__ __launch_bounds__(256) void out_gemm_kernel(const float* __restrict__ xf,
                                                       const float* __restrict__ Sg,
                                                       const float* __restrict__ u,
                                                       const float* __restrict__ v,
                                                       float* __restrict__ out)
{
    const int b = blockIdx.z;
    const float* A  = xf + (size_t)b * DD * NB;
    const float* Sb = Sg + (size_t)b * NB * NB;
    const float* ub = u + b * NB;
    const float* vb = v + b * NB;
    float*       ob = out + (size_t)b * DD * NB;

    const int i0 = blockIdx.x * 128;
    const int c0 = blockIdx.y * 128;

    __shared__ float As[8][132];   // As[k][cc] = xf[c0+cc][j0+k]
    __shared__ float Bs[8][132];   // Bs[k][ii] = attn[i0+ii][j0+k]

    const int tid = threadIdx.x;
    const int tx = tid & 15, ty = tid >> 4;
    const int lrow  = tid >> 1;        // 0..127
    const int lhalf = (tid & 1) * 4;   // 0 or 4

    float acc[8][8];
#pragma unroll
    for (int a = 0; a < 8; ++a)
#pragma unroll
        for (int q = 0; q < 8; ++q) acc[a][q] = 0.f;

    const float uu = ub[i0 + lrow];

    for (int j0 = 0; j0 < NB; j0 += 8) {
        float4 va = *(const float4*)&A [(size_t)(c0 + lrow) * NB + j0 + lhalf];
        float4 vs = *(const float4*)&Sb[(size_t)(i0 + lrow) * NB + j0 + lhalf];
        float4 vv = *(const float4*)&vb[j0 + lhalf];

        As[lhalf + 0][lrow] = va.x;
        As[lhalf + 1][lrow] = va.y;
        As[lhalf + 2][lrow] = va.z;
        As[lhalf + 3][lrow] = va.w;

        Bs[lhalf + 0][lrow] = __expf(vs.x + uu + vv.x);
        Bs[lhalf + 1][lrow] = __expf(vs.y + uu + vv.y);
        Bs[lhalf + 2][lrow] = __expf(vs.z + uu + vv.z);
        Bs[lhalf + 3][lrow] = __expf(vs.w + uu + vv.w);
        __syncthreads();
#pragma unroll
        for (int k = 0; k < 8; ++k) {
            float ra[8], rb[8];
            *(float4*)(ra)     = *(const float4*)&As[k][ty * 4];
            *(float4*)(ra + 4) = *(const float4*)&As[k][64 + ty * 4];
            *(float4*)(rb)     = *(const float4*)&Bs[k][tx * 4];
            *(float4*)(rb + 4) = *(const float4*)&Bs[k][64 + tx * 4];
#pragma unroll
            for (int a = 0; a < 8; ++a)
#pragma unroll
                for (int q = 0; q < 8; ++q)
                    acc[a][q] = fmaf(ra[a], rb[q], acc[a][q]);
        }
        __syncthreads();
    }

    // write: rows = c, cols = i (contiguous)
#pragma unroll
    for (int a = 0; a < 8; ++a) {
        int r = c0 + ((a < 4) ? (ty * 4 + a) : (64 + ty * 4 + a - 4));
        float4 w0 = make_float4(acc[a][0], acc[a][1], acc[a][2], acc[a][3]);
        float4 w1 = make_float4(acc[a][4], acc[a][5], acc[a][6], acc[a][7]);
        *(float4*)&ob[(size_t)r * NB + i0 + tx * 4]      = w0;
        *(float4*)&ob[(size_t)r * NB + i0 + 64 + tx * 4] = w1;
    }
}

// ---------------------------------------------------------------------------
extern "C" void kernel_launch(void* const* d_in, const int* in_sizes, int n_in,
                              void* d_out, int out_size)
{
    const float* x    = (const float*)d_in[0];
    const float* rowe = (const float*)d_in[1];
    const float* cole = (const float*)d_in[2];
    float* out = (float*)d_out;

    float* xf = g_xf;
    float* S  = g_S;
    float* u  = g_u;
    float* v  = g_v;

    // 1) xf = x + pos
    build_xf_kernel<<<(BB * DD * NB) / 256, 256>>>(x, rowe, cole, xf);

    // 2) S = xf^T xf / sqrt(d)   (symmetric, 36 upper-tri block pairs)
    s_gemm_kernel<<<dim3(36, BB), 256>>>(xf, S);

    // 3) u = -log n - rowLSE(S)
    row_lse_u_kernel<<<dim3(NB, BB), 256>>>(S, u);

    // 4) v = -log n - colLSE(S + u)   (via symmetry, row reads)
    col_lse_v_kernel<<<dim3(NB, BB), 256>>>(S, u, v);

    // 5) out = exp(S + u + v) @ xf, written back transposed
    out_gemm_kernel<<<dim3(NB / 128, DD / 128, BB), 256>>>(xf, S, u, v, out);
}

// round 7
// speedup vs baseline: 14.2341x; 14.2341x over previous
#include <cuda_runtime.h>
#include <cuda_bf16.h>
#include <math.h>
#include <stdint.h>

#define NB 1024   // n = H*W
#define DD 512    // d
#define BB 32     // batch

// ------------------------- device scratch (no allocs) -----------------------
// IMPORTANT: these are ONLY ever referenced from device code (never passed as
// kernel args from the host -- the host shadow symbol is a host address, and
// on GB300 ATS makes reads of it silently return zeros instead of faulting).
__device__ __nv_bfloat16 g_XI_hi[(size_t)BB * NB * DD];  // [b][i][c]
__device__ __nv_bfloat16 g_XI_lo[(size_t)BB * NB * DD];
__device__ __nv_bfloat16 g_XC_hi[(size_t)BB * DD * NB];  // [b][c][i]
__device__ __nv_bfloat16 g_XC_lo[(size_t)BB * DD * NB];
__device__ float         g_S   [(size_t)BB * NB * NB];   // [b][i][j]
__device__ __nv_bfloat16 g_AT_hi[(size_t)BB * NB * NB];  // [b][i][j]
__device__ __nv_bfloat16 g_AT_lo[(size_t)BB * NB * NB];
__device__ float         g_u[BB * NB];
__device__ float         g_v[BB * NB];

__device__ __forceinline__ uint32_t smem_u32(const void* p) {
    uint32_t a;
    asm("{ .reg .u64 t; cvta.to.shared.u64 t, %1; cvt.u32.u64 %0, t; }" : "=r"(a) : "l"(p));
    return a;
}

#define LDMATRIX_X4(r0, r1, r2, r3, addr) \
    asm volatile("ldmatrix.sync.aligned.m8n8.x4.shared.b16 {%0,%1,%2,%3}, [%4];" \
                 : "=r"(r0), "=r"(r1), "=r"(r2), "=r"(r3) : "r"(addr))

#define MMA_BF16(c, a, b) \
    asm volatile("mma.sync.aligned.m16n8k16.row.col.f32.bf16.bf16.f32 " \
                 "{%0,%1,%2,%3}, {%4,%5,%6,%7}, {%8,%9}, {%0,%1,%2,%3};" \
                 : "+f"((c)[0]), "+f"((c)[1]), "+f"((c)[2]), "+f"((c)[3]) \
                 : "r"((a)[0]), "r"((a)[1]), "r"((a)[2]), "r"((a)[3]), \
                   "r"((b)[0]), "r"((b)[1]))

// ---------------------------------------------------------------------------
// Kernel 1: pos-add + bf16 hi/lo split, stored in both layouts.
// ---------------------------------------------------------------------------
__global__ void split_kernel(const float* __restrict__ x,
                             const float* __restrict__ rowe,
                             const float* __restrict__ cole)
{
    const int b  = blockIdx.z;
    const int c0 = blockIdx.y * 32;
    const int i0 = blockIdx.x * 64;
    __shared__ __nv_bfloat16 shi[64][40];
    __shared__ __nv_bfloat16 slo[64][40];

    const int tid = threadIdx.x;
    const int tx = tid & 31;   // i-pair
    const int ty = tid >> 5;   // 0..7
    const size_t xbase = (size_t)b * DD * NB;

#pragma unroll
    for (int r = 0; r < 4; ++r) {
        int c = c0 + ty + r * 8;
        int i = i0 + tx * 2;
        float2 xv = *(const float2*)&x[xbase + (size_t)c * NB + i];
        int h0 = i >> 5, w0 = i & 31;
        int h1 = (i + 1) >> 5, w1 = (i + 1) & 31;
        float p0 = (c < 256) ? cole[w0 * 256 + c] : rowe[h0 * 256 + (c - 256)];
        float p1 = (c < 256) ? cole[w1 * 256 + c] : rowe[h1 * 256 + (c - 256)];
        float v0 = xv.x + p0, v1 = xv.y + p1;
        __nv_bfloat16 hb0 = __float2bfloat16(v0);
        __nv_bfloat16 lb0 = __float2bfloat16(v0 - __bfloat162float(hb0));
        __nv_bfloat16 hb1 = __float2bfloat16(v1);
        __nv_bfloat16 lb1 = __float2bfloat16(v1 - __bfloat162float(hb1));
        unsigned int hp = ((unsigned)__bfloat16_as_ushort(hb1) << 16) | __bfloat16_as_ushort(hb0);
        unsigned int lp = ((unsigned)__bfloat16_as_ushort(lb1) << 16) | __bfloat16_as_ushort(lb0);
        *(unsigned int*)&g_XC_hi[xbase + (size_t)c * NB + i] = hp;
        *(unsigned int*)&g_XC_lo[xbase + (size_t)c * NB + i] = lp;
        int cc = ty + r * 8;
        shi[tx * 2][cc] = hb0; shi[tx * 2 + 1][cc] = hb1;
        slo[tx * 2][cc] = lb0; slo[tx * 2 + 1][cc] = lb1;
    }
    __syncthreads();

    int ii = tid >> 2;
    int cs = (tid & 3) * 8;
    size_t obase = ((size_t)b * NB + i0 + ii) * DD + c0 + cs;
    uint4 ph, pl;
    unsigned short* hp = (unsigned short*)&ph;
    unsigned short* lp = (unsigned short*)&pl;
#pragma unroll
    for (int k = 0; k < 8; ++k) {
        hp[k] = __bfloat16_as_ushort(shi[ii][cs + k]);
        lp[k] = __bfloat16_as_ushort(slo[ii][cs + k]);
    }
    *(uint4*)&g_XI_hi[obase] = ph;
    *(uint4*)&g_XI_lo[obase] = pl;
}

// ---------------------------------------------------------------------------
// bf16x3 mma.sync GEMM:  D = scale * (Ahi+Alo) (Bhi+Blo)^T  (lo*lo dropped)
// CTA tile 128x128, BK=32, 8 warps (4m x 2n), each warp 32x64.
// MODE 0: S = XI XI^T / sqrt(d)   -> D = g_S        (device symbols bound here)
// MODE 1: out = XC AT^T           -> D = DoutParam  (harness pointer)
// ---------------------------------------------------------------------------
template<int KTOT, int MODE>
__global__ __launch_bounds__(256, 1)
void gemm_mma_kernel(float* __restrict__ DoutParam)
{
    __shared__ __nv_bfloat16 sAh[128][40];
    __shared__ __nv_bfloat16 sAl[128][40];
    __shared__ __nv_bfloat16 sBh[128][40];
    __shared__ __nv_bfloat16 sBl[128][40];

    const int tid  = threadIdx.x;
    const int wid  = tid >> 5;
    const int lane = tid & 31;
    const int wm   = wid >> 1;            // 0..3  (rows wm*32 .. +32)
    const int wn   = wid & 1;             // 0..1  (cols wn*64 .. +64)
    const int b  = blockIdx.z;
    const int n0 = blockIdx.x * 128;
    const int m0 = blockIdx.y * 128;

    const __nv_bfloat16 *Ahg, *Alg, *Bhg, *Blg;
    float* Dg;
    float scale;
    size_t Abstr, Bbstr, Dbstr;
    if constexpr (MODE == 0) {
        Ahg = g_XI_hi; Alg = g_XI_lo; Bhg = g_XI_hi; Blg = g_XI_lo;
        Dg = g_S; scale = 0.044194173824159216f;     // 1/sqrt(512)
        Abstr = (size_t)NB * DD; Bbstr = (size_t)NB * DD; Dbstr = (size_t)NB * NB;
    } else {
        Ahg = g_XC_hi; Alg = g_XC_lo; Bhg = g_AT_hi; Blg = g_AT_lo;
        Dg = DoutParam; scale = 1.0f;
        Abstr = (size_t)DD * NB; Bbstr = (size_t)NB * NB; Dbstr = (size_t)DD * NB;
    }
    const int ldD = NB;

    const __nv_bfloat16* Ah = Ahg + (size_t)b * Abstr + (size_t)m0 * KTOT;
    const __nv_bfloat16* Al = Alg + (size_t)b * Abstr + (size_t)m0 * KTOT;
    const __nv_bfloat16* Bh = Bhg + (size_t)b * Bbstr + (size_t)n0 * KTOT;
    const __nv_bfloat16* Bl = Blg + (size_t)b * Bbstr + (size_t)n0 * KTOT;

    const int lrow = tid >> 1;
    const int lseg = (tid & 1) * 16;

    float acc[2][8][4];
#pragma unroll
    for (int mt = 0; mt < 2; ++mt)
#pragma unroll
        for (int nt = 0; nt < 8; ++nt)
#pragma unroll
            for (int q = 0; q < 4; ++q) acc[mt][nt][q] = 0.f;

    const uint32_t sa_h = smem_u32(&sAh[0][0]);
    const uint32_t sa_l = smem_u32(&sAl[0][0]);
    const uint32_t sb_h = smem_u32(&sBh[0][0]);
    const uint32_t sb_l = smem_u32(&sBl[0][0]);

    for (int kc = 0; kc < KTOT; kc += 32) {
        {
            const size_t go = (size_t)lrow * KTOT + kc + lseg;
            uint4 a0 = *(const uint4*)&Ah[go];
            uint4 a1 = *(const uint4*)&Ah[go + 8];
            uint4 c0 = *(const uint4*)&Al[go];
            uint4 c1 = *(const uint4*)&Al[go + 8];
            uint4 b0 = *(const uint4*)&Bh[go];
            uint4 b1 = *(const uint4*)&Bh[go + 8];
            uint4 d0 = *(const uint4*)&Bl[go];
            uint4 d1 = *(const uint4*)&Bl[go + 8];
            *(uint4*)&sAh[lrow][lseg] = a0;  *(uint4*)&sAh[lrow][lseg + 8] = a1;
            *(uint4*)&sAl[lrow][lseg] = c0;  *(uint4*)&sAl[lrow][lseg + 8] = c1;
            *(uint4*)&sBh[lrow][lseg] = b0;  *(uint4*)&sBh[lrow][lseg + 8] = b1;
            *(uint4*)&sBl[lrow][lseg] = d0;  *(uint4*)&sBl[lrow][lseg + 8] = d1;
        }
        __syncthreads();

#pragma unroll
        for (int ks = 0; ks < 2; ++ks) {
            const int k0 = ks * 16;
            uint32_t fAh[2][4], fAl[2][4];
#pragma unroll
            for (int mt = 0; mt < 2; ++mt) {
                int row = wm * 32 + mt * 16 + (lane & 15);
                uint32_t off = (uint32_t)(row * 40 + k0 + (lane >> 4) * 8) * 2u;
                LDMATRIX_X4(fAh[mt][0], fAh[mt][1], fAh[mt][2], fAh[mt][3], sa_h + off);
                LDMATRIX_X4(fAl[mt][0], fAl[mt][1], fAl[mt][2], fAl[mt][3], sa_l + off);
            }
#pragma unroll
            for (int p = 0; p < 4; ++p) {
                int nrow = wn * 64 + p * 16 + (lane & 15);
                uint32_t off = (uint32_t)(nrow * 40 + k0 + (lane >> 4) * 8) * 2u;
                uint32_t h0, h1, h2, h3, l0, l1, l2, l3;
                LDMATRIX_X4(h0, h1, h2, h3, sb_h + off);
                LDMATRIX_X4(l0, l1, l2, l3, sb_l + off);
                uint32_t bh0[2] = {h0, h2}, bh1[2] = {h1, h3};
                uint32_t bl0[2] = {l0, l2}, bl1[2] = {l1, l3};
#pragma unroll
                for (int mt = 0; mt < 2; ++mt) {
                    MMA_BF16(acc[mt][2 * p],     fAh[mt], bh0);
                    MMA_BF16(acc[mt][2 * p],     fAh[mt], bl0);
                    MMA_BF16(acc[mt][2 * p],     fAl[mt], bh0);
                    MMA_BF16(acc[mt][2 * p + 1], fAh[mt], bh1);
                    MMA_BF16(acc[mt][2 * p + 1], fAh[mt], bl1);
                    MMA_BF16(acc[mt][2 * p + 1], fAl[mt], bh1);
                }
            }
        }
        __syncthreads();
    }

    float* Db = Dg + (size_t)b * Dbstr;
#pragma unroll
    for (int mt = 0; mt < 2; ++mt) {
        int r0 = m0 + wm * 32 + mt * 16 + (lane >> 2);
#pragma unroll
        for (int nt = 0; nt < 8; ++nt) {
            int c = n0 + wn * 64 + nt * 8 + (lane & 3) * 2;
            float2 w0 = make_float2(acc[mt][nt][0] * scale, acc[mt][nt][1] * scale);
            float2 w1 = make_float2(acc[mt][nt][2] * scale, acc[mt][nt][3] * scale);
            *(float2*)&Db[(size_t)r0 * ldD + c]       = w0;
            *(float2*)&Db[(size_t)(r0 + 8) * ldD + c] = w1;
        }
    }
}

// ---------------------------------------------------------------------------
// u[b][i] = -log n - LSE_j S[b][i][:]   (warp per row)
// ---------------------------------------------------------------------------
__global__ void u_lse_kernel()
{
    const int gw   = blockIdx.x * 8 + (threadIdx.x >> 5);
    const int lane = threadIdx.x & 31;
    const float4* row = (const float4*)&g_S[(size_t)gw * NB];

    float4 V[8];
#pragma unroll
    for (int s = 0; s < 8; ++s) V[s] = row[lane + 32 * s];

    float m = -1e30f;
#pragma unroll
    for (int s = 0; s < 8; ++s)
        m = fmaxf(m, fmaxf(fmaxf(V[s].x, V[s].y), fmaxf(V[s].z, V[s].w)));
#pragma unroll
    for (int o = 16; o > 0; o >>= 1) m = fmaxf(m, __shfl_xor_sync(~0u, m, o));

    float sum = 0.f;
#pragma unroll
    for (int s = 0; s < 8; ++s)
        sum += __expf(V[s].x - m) + __expf(V[s].y - m) + __expf(V[s].z - m) + __expf(V[s].w - m);
#pragma unroll
    for (int o = 16; o > 0; o >>= 1) sum += __shfl_xor_sync(~0u, sum, o);

    if (lane == 0) g_u[gw] = -6.9314718055994531f - (m + logf(sum));
}

// ---------------------------------------------------------------------------
// v[b][j] = -log n - LSE_i (S[b][i][j] + u[b][i])  via symmetry (row j)
// ---------------------------------------------------------------------------
__global__ void v_lse_kernel()
{
    const int gw   = blockIdx.x * 8 + (threadIdx.x >> 5);
    const int lane = threadIdx.x & 31;
    const int b    = gw >> 10;
    const float4* row = (const float4*)&g_S[(size_t)gw * NB];
    const float4* urw = (const float4*)&g_u[b * NB];

    float4 V[8];
#pragma unroll
    for (int s = 0; s < 8; ++s) {
        float4 sv = row[lane + 32 * s];
        float4 uv = urw[lane + 32 * s];
        V[s].x = sv.x + uv.x; V[s].y = sv.y + uv.y;
        V[s].z = sv.z + uv.z; V[s].w = sv.w + uv.w;
    }
    float m = -1e30f;
#pragma unroll
    for (int s = 0; s < 8; ++s)
        m = fmaxf(m, fmaxf(fmaxf(V[s].x, V[s].y), fmaxf(V[s].z, V[s].w)));
#pragma unroll
    for (int o = 16; o > 0; o >>= 1) m = fmaxf(m, __shfl_xor_sync(~0u, m, o));

    float sum = 0.f;
#pragma unroll
    for (int s = 0; s < 8; ++s)
        sum += __expf(V[s].x - m) + __expf(V[s].y - m) + __expf(V[s].z - m) + __expf(V[s].w - m);
#pragma unroll
    for (int o = 16; o > 0; o >>= 1) sum += __shfl_xor_sync(~0u, sum, o);

    if (lane == 0) g_v[gw] = -6.9314718055994531f - (m + logf(sum));
}

// ---------------------------------------------------------------------------
// attn = exp(S + u_i + v_j), split to bf16 hi/lo
// ---------------------------------------------------------------------------
__global__ void attn_split_kernel()
{
    const size_t idx = (size_t)blockIdx.x * 256 + threadIdx.x;  // float4 index
    const int j4 = (int)(idx & 255);
    const int i  = (int)((idx >> 8) & 1023);
    const int b  = (int)(idx >> 18);
    const size_t off = ((size_t)b * NB + i) * NB + (size_t)j4 * 4;

    float4 s4 = *(const float4*)&g_S[off];
    float  uu = g_u[b * NB + i];
    float4 vv = *(const float4*)&g_v[b * NB + j4 * 4];

    float e0 = __expf(s4.x + uu + vv.x);
    float e1 = __expf(s4.y + uu + vv.y);
    float e2 = __expf(s4.z + uu + vv.z);
    float e3 = __expf(s4.w + uu + vv.w);

    __nv_bfloat16 h0 = __float2bfloat16(e0), h1 = __float2bfloat16(e1);
    __nv_bfloat16 h2 = __float2bfloat16(e2), h3 = __float2bfloat16(e3);
    __nv_bfloat16 l0 = __float2bfloat16(e0 - __bfloat162float(h0));
    __nv_bfloat16 l1 = __float2bfloat16(e1 - __bfloat162float(h1));
    __nv_bfloat16 l2 = __float2bfloat16(e2 - __bfloat162float(h2));
    __nv_bfloat16 l3 = __float2bfloat16(e3 - __bfloat162float(h3));

    uint2 H, L;
    H.x = ((unsigned)__bfloat16_as_ushort(h1) << 16) | __bfloat16_as_ushort(h0);
    H.y = ((unsigned)__bfloat16_as_ushort(h3) << 16) | __bfloat16_as_ushort(h2);
    L.x = ((unsigned)__bfloat16_as_ushort(l1) << 16) | __bfloat16_as_ushort(l0);
    L.y = ((unsigned)__bfloat16_as_ushort(l3) << 16) | __bfloat16_as_ushort(l2);
    *(uint2*)&g_AT_hi[off] = H;
    *(uint2*)&g_AT_lo[off] = L;
}

// ---------------------------------------------------------------------------
extern "C" void kernel_launch(void* const* d_in, const int* in_sizes, int n_in,
                              void* d_out, int out_size)
{
    const float* x    = (const float*)d_in[0];
    const float* rowe = (const float*)d_in[1];
    const float* cole = (const float*)d_in[2];
    float* out = (float*)d_out;

    // 1) pos add + bf16 split, both layouts (writes device globals directly)
    split_kernel<<<dim3(NB / 64, DD / 32, BB), 256>>>(x, rowe, cole);

    // 2) S = XI XI^T / sqrt(d)  -- mma.sync bf16x3 (scratch bound device-side)
    gemm_mma_kernel<512, 0><<<dim3(8, 8, BB), 256>>>(nullptr);

    // 3) u = -log n - rowLSE(S)
    u_lse_kernel<<<BB * NB / 8, 256>>>();

    // 4) v = -log n - colLSE(S + u)  (symmetry)
    v_lse_kernel<<<BB * NB / 8, 256>>>();

    // 5) attn = exp(S + u + v), bf16 split
    attn_split_kernel<<<(int)((size_t)BB * NB * NB / 4 / 256), 256>>>();

    // 6) out = XC AT^T  -- mma.sync bf16x3 (only d_out crosses the boundary)
    gemm_mma_kernel<1024, 1><<<dim3(8, 4, BB), 256>>>(out);
}

// round 11
// speedup vs baseline: 17.3224x; 1.2170x over previous
#include <cuda_runtime.h>
#include <cuda_bf16.h>
#include <math.h>
#include <stdint.h>

#define NB 1024   // n = H*W
#define DD 512    // d
#define BB 32     // batch

// ------------------------- device scratch (no allocs) -----------------------
// ONLY referenced from device code (host shadow symbols are poison under ATS).
__device__ __nv_bfloat16 g_XI_hi[(size_t)BB * NB * DD];  // [b][i][c]
__device__ __nv_bfloat16 g_XI_lo[(size_t)BB * NB * DD];
__device__ __nv_bfloat16 g_XC_hi[(size_t)BB * DD * NB];  // [b][c][i]
__device__ __nv_bfloat16 g_XC_lo[(size_t)BB * DD * NB];
__device__ float         g_S   [(size_t)BB * NB * NB];   // [b][i][j]
__device__ float         g_u[BB * NB];
__device__ float         g_v[BB * NB];

__device__ __forceinline__ uint32_t smem_u32(const void* p) {
    uint32_t a;
    asm("{ .reg .u64 t; cvta.to.shared.u64 t, %1; cvt.u32.u64 %0, t; }" : "=r"(a) : "l"(p));
    return a;
}

#define LDMATRIX_X4(r0, r1, r2, r3, addr) \
    asm volatile("ldmatrix.sync.aligned.m8n8.x4.shared.b16 {%0,%1,%2,%3}, [%4];" \
                 : "=r"(r0), "=r"(r1), "=r"(r2), "=r"(r3) : "r"(addr))

#define MMA_BF16(c, a, b) \
    asm volatile("mma.sync.aligned.m16n8k16.row.col.f32.bf16.bf16.f32 " \
                 "{%0,%1,%2,%3}, {%4,%5,%6,%7}, {%8,%9}, {%0,%1,%2,%3};" \
                 : "+f"((c)[0]), "+f"((c)[1]), "+f"((c)[2]), "+f"((c)[3]) \
                 : "r"((a)[0]), "r"((a)[1]), "r"((a)[2]), "r"((a)[3]), \
                   "r"((b)[0]), "r"((b)[1]))

#define CP_ASYNC16(sm, gp) \
    asm volatile("cp.async.cg.shared.global [%0], [%1], 16;" :: "r"(sm), "l"(gp))
#define CP_COMMIT() asm volatile("cp.async.commit_group;" ::: "memory")
#define CP_WAIT1()  asm volatile("cp.async.wait_group 1;" ::: "memory")
#define CP_WAIT0()  asm volatile("cp.async.wait_group 0;" ::: "memory")

// ---------------------------------------------------------------------------
// Kernel 1: pos-add + bf16 hi/lo split, stored in both layouts.
// ---------------------------------------------------------------------------
__global__ void split_kernel(const float* __restrict__ x,
                             const float* __restrict__ rowe,
                             const float* __restrict__ cole)
{
    const int b  = blockIdx.z;
    const int c0 = blockIdx.y * 32;
    const int i0 = blockIdx.x * 64;
    __shared__ __nv_bfloat16 shi[64][40];
    __shared__ __nv_bfloat16 slo[64][40];

    const int tid = threadIdx.x;
    const int tx = tid & 31;
    const int ty = tid >> 5;
    const size_t xbase = (size_t)b * DD * NB;

#pragma unroll
    for (int r = 0; r < 4; ++r) {
        int c = c0 + ty + r * 8;
        int i = i0 + tx * 2;
        float2 xv = *(const float2*)&x[xbase + (size_t)c * NB + i];
        int h0 = i >> 5, w0 = i & 31;
        int h1 = (i + 1) >> 5, w1 = (i + 1) & 31;
        float p0 = (c < 256) ? cole[w0 * 256 + c] : rowe[h0 * 256 + (c - 256)];
        float p1 = (c < 256) ? cole[w1 * 256 + c] : rowe[h1 * 256 + (c - 256)];
        float v0 = xv.x + p0, v1 = xv.y + p1;
        __nv_bfloat16 hb0 = __float2bfloat16(v0);
        __nv_bfloat16 lb0 = __float2bfloat16(v0 - __bfloat162float(hb0));
        __nv_bfloat16 hb1 = __float2bfloat16(v1);
        __nv_bfloat16 lb1 = __float2bfloat16(v1 - __bfloat162float(hb1));
        unsigned int hp = ((unsigned)__bfloat16_as_ushort(hb1) << 16) | __bfloat16_as_ushort(hb0);
        unsigned int lp = ((unsigned)__bfloat16_as_ushort(lb1) << 16) | __bfloat16_as_ushort(lb0);
        *(unsigned int*)&g_XC_hi[xbase + (size_t)c * NB + i] = hp;
        *(unsigned int*)&g_XC_lo[xbase + (size_t)c * NB + i] = lp;
        int cc = ty + r * 8;
        shi[tx * 2][cc] = hb0; shi[tx * 2 + 1][cc] = hb1;
        slo[tx * 2][cc] = lb0; slo[tx * 2 + 1][cc] = lb1;
    }
    __syncthreads();

    int ii = tid >> 2;
    int cs = (tid & 3) * 8;
    size_t obase = ((size_t)b * NB + i0 + ii) * DD + c0 + cs;
    uint4 ph, pl;
    unsigned short* hp = (unsigned short*)&ph;
    unsigned short* lp = (unsigned short*)&pl;
#pragma unroll
    for (int k = 0; k < 8; ++k) {
        hp[k] = __bfloat16_as_ushort(shi[ii][cs + k]);
        lp[k] = __bfloat16_as_ushort(slo[ii][cs + k]);
    }
    *(uint4*)&g_XI_hi[obase] = ph;
    *(uint4*)&g_XI_lo[obase] = pl;
}

// ---------------------------------------------------------------------------
// GEMM1: S = XI XI^T / sqrt(d). Symmetric: 36 upper-tri block pairs, mirror
// write via smem transpose. cp.async double-buffered, bf16x3 mma.sync.
// dyn smem: 4 arrays x 2 stages x (128*40 bf16 = 10240B) = 81920 B
//           (reused at end as 128x129 f32 transpose buffer: 66048 B)
// ---------------------------------------------------------------------------
__global__ __launch_bounds__(256, 2)
void s_gemm_kernel()
{
    extern __shared__ char dyn[];
    const uint32_t sbase = smem_u32(dyn);
    // layout: [stage][array] array order: Ah, Al, Bh, Bl ; each 10240 B
    const int tid  = threadIdx.x;
    const int wid  = tid >> 5;
    const int lane = tid & 31;
    const int wm   = wid >> 1;
    const int wn   = wid & 1;
    const int b = blockIdx.y;

    int t = blockIdx.x, bi = 0;
    while (t >= 8 - bi) { t -= 8 - bi; ++bi; }
    const int bj = bi + t;
    const int m0 = bi * 128, n0 = bj * 128;

    const __nv_bfloat16* Ah = g_XI_hi + (size_t)b * NB * DD + (size_t)m0 * DD;
    const __nv_bfloat16* Al = g_XI_lo + (size_t)b * NB * DD + (size_t)m0 * DD;
    const __nv_bfloat16* Bh = g_XI_hi + (size_t)b * NB * DD + (size_t)n0 * DD;
    const __nv_bfloat16* Bl = g_XI_lo + (size_t)b * NB * DD + (size_t)n0 * DD;

    float acc[2][8][4];
#pragma unroll
    for (int mt = 0; mt < 2; ++mt)
#pragma unroll
        for (int nt = 0; nt < 8; ++nt)
#pragma unroll
            for (int q = 0; q < 4; ++q) acc[mt][nt][q] = 0.f;

    // cp.async stage: per array 2 passes; q=pass*256+tid -> row=q>>2, seg=q&3
    auto stage = [&](int p, int kc) {
        const uint32_t sb = sbase + (uint32_t)p * 40960u;
        const __nv_bfloat16* srcs[4] = {Ah, Al, Bh, Bl};
#pragma unroll
        for (int a = 0; a < 4; ++a) {
            const __nv_bfloat16* g = srcs[a] + kc;
            const uint32_t ab = sb + (uint32_t)a * 10240u;
#pragma unroll
            for (int pass = 0; pass < 2; ++pass) {
                int q = pass * 256 + tid;
                int row = q >> 2, seg = q & 3;
                CP_ASYNC16(ab + (uint32_t)(row * 80 + seg * 16),
                           g + (size_t)row * DD + seg * 8);
            }
        }
        CP_COMMIT();
    };

    stage(0, 0);
    const int NCH = DD / 32;     // 16
    for (int kci = 0; kci < NCH; ++kci) {
        const int p = kci & 1;
        if (kci + 1 < NCH) stage(p ^ 1, (kci + 1) * 32);
        if (kci + 1 < NCH) { CP_WAIT1(); } else { CP_WAIT0(); }
        __syncthreads();

        const uint32_t sb = sbase + (uint32_t)p * 40960u;
        const uint32_t sa_h = sb, sa_l = sb + 10240u, sb_h = sb + 20480u, sb_l = sb + 30720u;
#pragma unroll
        for (int ks = 0; ks < 2; ++ks) {
            const int k0 = ks * 16;
            uint32_t fAh[2][4], fAl[2][4];
#pragma unroll
            for (int mt = 0; mt < 2; ++mt) {
                int row = wm * 32 + mt * 16 + (lane & 15);
                uint32_t off = (uint32_t)(row * 40 + k0 + (lane >> 4) * 8) * 2u;
                LDMATRIX_X4(fAh[mt][0], fAh[mt][1], fAh[mt][2], fAh[mt][3], sa_h + off);
                LDMATRIX_X4(fAl[mt][0], fAl[mt][1], fAl[mt][2], fAl[mt][3], sa_l + off);
            }
#pragma unroll
            for (int pp = 0; pp < 4; ++pp) {
                int nrow = wn * 64 + pp * 16 + (lane & 15);
                uint32_t off = (uint32_t)(nrow * 40 + k0 + (lane >> 4) * 8) * 2u;
                uint32_t h0, h1, h2, h3, l0, l1, l2, l3;
                LDMATRIX_X4(h0, h1, h2, h3, sb_h + off);
                LDMATRIX_X4(l0, l1, l2, l3, sb_l + off);
                uint32_t bh0[2] = {h0, h2}, bh1[2] = {h1, h3};
                uint32_t bl0[2] = {l0, l2}, bl1[2] = {l1, l3};
#pragma unroll
                for (int mt = 0; mt < 2; ++mt) {
                    MMA_BF16(acc[mt][2 * pp],     fAh[mt], bh0);
                    MMA_BF16(acc[mt][2 * pp],     fAh[mt], bl0);
                    MMA_BF16(acc[mt][2 * pp],     fAl[mt], bh0);
                    MMA_BF16(acc[mt][2 * pp + 1], fAh[mt], bh1);
                    MMA_BF16(acc[mt][2 * pp + 1], fAh[mt], bl1);
                    MMA_BF16(acc[mt][2 * pp + 1], fAl[mt], bh1);
                }
            }
        }
        __syncthreads();
    }

    const float scale = 0.044194173824159216f; // 1/sqrt(512)
    float* Sb = g_S + (size_t)b * NB * NB;

    // normal write (rows m0+, cols n0+, coalesced) + scale applied
#pragma unroll
    for (int mt = 0; mt < 2; ++mt) {
        int r0 = m0 + wm * 32 + mt * 16 + (lane >> 2);
#pragma unroll
        for (int nt = 0; nt < 8; ++nt) {
            int c = n0 + wn * 64 + nt * 8 + (lane & 3) * 2;
            float2 w0 = make_float2(acc[mt][nt][0] * scale, acc[mt][nt][1] * scale);
            float2 w1 = make_float2(acc[mt][nt][2] * scale, acc[mt][nt][3] * scale);
            *(float2*)&Sb[(size_t)r0 * NB + c]       = w0;
            *(float2*)&Sb[(size_t)(r0 + 8) * NB + c] = w1;
        }
    }

    if (bi != bj) {
        // transpose via smem (pad 129 -> conflict-free column reads)
        float* Tsm = (float*)dyn;
#pragma unroll
        for (int mt = 0; mt < 2; ++mt) {
            int lr = wm * 32 + mt * 16 + (lane >> 2);
#pragma unroll
            for (int nt = 0; nt < 8; ++nt) {
                int lc = wn * 64 + nt * 8 + (lane & 3) * 2;
                Tsm[lr * 129 + lc]           = acc[mt][nt][0] * scale;
                Tsm[lr * 129 + lc + 1]       = acc[mt][nt][1] * scale;
                Tsm[(lr + 8) * 129 + lc]     = acc[mt][nt][2] * scale;
                Tsm[(lr + 8) * 129 + lc + 1] = acc[mt][nt][3] * scale;
            }
        }
        __syncthreads();
        int jr = tid >> 1;             // 0..127 : local col -> global row n0+jr
        int hh = (tid & 1) * 64;       // half of 128 outputs
        float* dst = &Sb[(size_t)(n0 + jr) * NB + m0 + hh];
#pragma unroll
        for (int k0 = 0; k0 < 64; k0 += 4) {
            float4 w;
            w.x = Tsm[(hh + k0 + 0) * 129 + jr];
            w.y = Tsm[(hh + k0 + 1) * 129 + jr];
            w.z = Tsm[(hh + k0 + 2) * 129 + jr];
            w.w = Tsm[(hh + k0 + 3) * 129 + jr];
            *(float4*)&dst[k0] = w;
        }
    }
}

// ---------------------------------------------------------------------------
// GEMM2: out[b][c][i] = sum_j XC[c][j] * exp(S[i][j]+u[i]+v[j])
// B tile computed on the fly from S (fp32, cp.async staged) -> bf16 hi/lo smem.
// dyn smem layout:
//   0      : sA  [2 stages][Ah,Al][128*40 bf16]   = 40960 B
//   40960  : sS  [2 stages][128*36 f32 (144B/row)]= 36864 B
//   77824  : sBh [128*40 bf16] = 10240 B
//   88064  : sBl [128*40 bf16] = 10240 B
//   total 98304 B
// ---------------------------------------------------------------------------
__global__ __launch_bounds__(256, 2)
void out_gemm_kernel(float* __restrict__ Dout)
{
    extern __shared__ char dyn[];
    const uint32_t sbase = smem_u32(dyn);
    const uint32_t sS0 = sbase + 40960u;
    const uint32_t sb_h = sbase + 77824u;
    const uint32_t sb_l = sbase + 88064u;

    const int tid  = threadIdx.x;
    const int wid  = tid >> 5;
    const int lane = tid & 31;
    const int wm   = wid >> 1;
    const int wn   = wid & 1;
    const int b  = blockIdx.z;
    const int n0 = blockIdx.x * 128;   // i block
    const int m0 = blockIdx.y * 128;   // c block

    const __nv_bfloat16* Ah = g_XC_hi + (size_t)b * DD * NB + (size_t)m0 * NB;
    const __nv_bfloat16* Al = g_XC_lo + (size_t)b * DD * NB + (size_t)m0 * NB;
    const float* Sb = g_S + (size_t)b * NB * NB + (size_t)n0 * NB;
    const float* ub = g_u + b * NB + n0;
    const float* vb = g_v + b * NB;

    float acc[2][8][4];
#pragma unroll
    for (int mt = 0; mt < 2; ++mt)
#pragma unroll
        for (int nt = 0; nt < 8; ++nt)
#pragma unroll
            for (int q = 0; q < 4; ++q) acc[mt][nt][q] = 0.f;

    auto stage = [&](int p, int kc) {
        // A hi/lo: 2 passes each
        const __nv_bfloat16* srcs[2] = {Ah, Al};
#pragma unroll
        for (int a = 0; a < 2; ++a) {
            const __nv_bfloat16* g = srcs[a] + kc;
            const uint32_t ab = sbase + (uint32_t)p * 20480u + (uint32_t)a * 10240u;
#pragma unroll
            for (int pass = 0; pass < 2; ++pass) {
                int q = pass * 256 + tid;
                int row = q >> 2, seg = q & 3;
                CP_ASYNC16(ab + (uint32_t)(row * 80 + seg * 16),
                           g + (size_t)row * NB + seg * 8);
            }
        }
        // S: 128 rows x 128B, 4 passes ; q -> row=q>>3, seg=q&7
        const float* gs = Sb + kc;
        const uint32_t ss = sS0 + (uint32_t)p * 18432u;
#pragma unroll
        for (int pass = 0; pass < 4; ++pass) {
            int q = pass * 256 + tid;
            int row = q >> 3, seg = q & 7;
            CP_ASYNC16(ss + (uint32_t)(row * 144 + seg * 16),
                       gs + (size_t)row * NB + seg * 4);
        }
        CP_COMMIT();
    };

    const float uu = ub[tid >> 1];     // row handled by this thread in transform
    stage(0, 0);
    const int NCH = NB / 32;           // 32
    for (int kci = 0; kci < NCH; ++kci) {
        const int p = kci & 1;
        const int kc = kci * 32;
        if (kci + 1 < NCH) stage(p ^ 1, kc + 32);
        if (kci + 1 < NCH) { CP_WAIT1(); } else { CP_WAIT0(); }
        __syncthreads();

        // ---- transform: sB = split(exp(S + u + v)) ----
        {
            const int row = tid >> 1, half = tid & 1;
            const uint32_t srow = sS0 + (uint32_t)p * 18432u + (uint32_t)(row * 144 + half * 64);
            float sv[16];
#pragma unroll
            for (int q4 = 0; q4 < 4; ++q4) {
                float4 s4;
                asm volatile("ld.shared.v4.f32 {%0,%1,%2,%3}, [%4];"
                             : "=f"(s4.x), "=f"(s4.y), "=f"(s4.z), "=f"(s4.w)
                             : "r"(srow + (uint32_t)(q4 * 16)));
                sv[q4 * 4 + 0] = s4.x; sv[q4 * 4 + 1] = s4.y;
                sv[q4 * 4 + 2] = s4.z; sv[q4 * 4 + 3] = s4.w;
            }
            const float* vp = vb + kc + half * 16;
            uint32_t hp[8], lp[8];
#pragma unroll
            for (int e = 0; e < 8; ++e) {
                float e0 = __expf(sv[2 * e]     + uu + vp[2 * e]);
                float e1 = __expf(sv[2 * e + 1] + uu + vp[2 * e + 1]);
                __nv_bfloat16 h0 = __float2bfloat16(e0);
                __nv_bfloat16 h1 = __float2bfloat16(e1);
                __nv_bfloat16 l0 = __float2bfloat16(e0 - __bfloat162float(h0));
                __nv_bfloat16 l1 = __float2bfloat16(e1 - __bfloat162float(h1));
                hp[e] = ((unsigned)__bfloat16_as_ushort(h1) << 16) | __bfloat16_as_ushort(h0);
                lp[e] = ((unsigned)__bfloat16_as_ushort(l1) << 16) | __bfloat16_as_ushort(l0);
            }
            const uint32_t bo = (uint32_t)(row * 80 + half * 32);
#pragma unroll
            for (int q4 = 0; q4 < 2; ++q4) {
                asm volatile("st.shared.v4.b32 [%0], {%1,%2,%3,%4};"
                             :: "r"(sb_h + bo + q4 * 16), "r"(hp[q4*4]), "r"(hp[q4*4+1]),
                                "r"(hp[q4*4+2]), "r"(hp[q4*4+3]));
                asm volatile("st.shared.v4.b32 [%0], {%1,%2,%3,%4};"
                             :: "r"(sb_l + bo + q4 * 16), "r"(lp[q4*4]), "r"(lp[q4*4+1]),
                                "r"(lp[q4*4+2]), "r"(lp[q4*4+3]));
            }
        }
        __syncthreads();

        // ---- MMAs ----
        const uint32_t sa_h = sbase + (uint32_t)p * 20480u;
        const uint32_t sa_l = sa_h + 10240u;
#pragma unroll
        for (int ks = 0; ks < 2; ++ks) {
            const int k0 = ks * 16;
            uint32_t fAh[2][4], fAl[2][4];
#pragma unroll
            for (int mt = 0; mt < 2; ++mt) {
                int row = wm * 32 + mt * 16 + (lane & 15);
                uint32_t off = (uint32_t)(row * 40 + k0 + (lane >> 4) * 8) * 2u;
                LDMATRIX_X4(fAh[mt][0], fAh[mt][1], fAh[mt][2], fAh[mt][3], sa_h + off);
                LDMATRIX_X4(fAl[mt][0], fAl[mt][1], fAl[mt][2], fAl[mt][3], sa_l + off);
            }
#pragma unroll
            for (int pp = 0; pp < 4; ++pp) {
                int nrow = wn * 64 + pp * 16 + (lane & 15);
                uint32_t off = (uint32_t)(nrow * 40 + k0 + (lane >> 4) * 8) * 2u;
                uint32_t h0, h1, h2, h3, l0, l1, l2, l3;
                LDMATRIX_X4(h0, h1, h2, h3, sb_h + off);
                LDMATRIX_X4(l0, l1, l2, l3, sb_l + off);
                uint32_t bh0[2] = {h0, h2}, bh1[2] = {h1, h3};
                uint32_t bl0[2] = {l0, l2}, bl1[2] = {l1, l3};
#pragma unroll
                for (int mt = 0; mt < 2; ++mt) {
                    MMA_BF16(acc[mt][2 * pp],     fAh[mt], bh0);
                    MMA_BF16(acc[mt][2 * pp],     fAh[mt], bl0);
                    MMA_BF16(acc[mt][2 * pp],     fAl[mt], bh0);
                    MMA_BF16(acc[mt][2 * pp + 1], fAh[mt], bh1);
                    MMA_BF16(acc[mt][2 * pp + 1], fAh[mt], bl1);
                    MMA_BF16(acc[mt][2 * pp + 1], fAl[mt], bh1);
                }
            }
        }
        __syncthreads();
    }

    float* Db = Dout + (size_t)b * DD * NB;
#pragma unroll
    for (int mt = 0; mt < 2; ++mt) {
        int r0 = m0 + wm * 32 + mt * 16 + (lane >> 2);
#pragma unroll
        for (int nt = 0; nt < 8; ++nt) {
            int c = n0 + wn * 64 + nt * 8 + (lane & 3) * 2;
            float2 w0 = make_float2(acc[mt][nt][0], acc[mt][nt][1]);
            float2 w1 = make_float2(acc[mt][nt][2], acc[mt][nt][3]);
            *(float2*)&Db[(size_t)r0 * NB + c]       = w0;
            *(float2*)&Db[(size_t)(r0 + 8) * NB + c] = w1;
        }
    }
}

// ---------------------------------------------------------------------------
// u[b][i] = -log n - LSE_j S[b][i][:]   (warp per row)
// ---------------------------------------------------------------------------
__global__ void u_lse_kernel()
{
    const int gw   = blockIdx.x * 8 + (threadIdx.x >> 5);
    const int lane = threadIdx.x & 31;
    const float4* row = (const float4*)&g_S[(size_t)gw * NB];

    float4 V[8];
#pragma unroll
    for (int s = 0; s < 8; ++s) V[s] = row[lane + 32 * s];

    float m = -1e30f;
#pragma unroll
    for (int s = 0; s < 8; ++s)
        m = fmaxf(m, fmaxf(fmaxf(V[s].x, V[s].y), fmaxf(V[s].z, V[s].w)));
#pragma unroll
    for (int o = 16; o > 0; o >>= 1) m = fmaxf(m, __shfl_xor_sync(~0u, m, o));

    float sum = 0.f;
#pragma unroll
    for (int s = 0; s < 8; ++s)
        sum += __expf(V[s].x - m) + __expf(V[s].y - m) + __expf(V[s].z - m) + __expf(V[s].w - m);
#pragma unroll
    for (int o = 16; o > 0; o >>= 1) sum += __shfl_xor_sync(~0u, sum, o);

    if (lane == 0) g_u[gw] = -6.9314718055994531f - (m + logf(sum));
}

// ---------------------------------------------------------------------------
// v[b][j] = -log n - LSE_i (S[b][i][j] + u[b][i])  via symmetry (row j)
// ---------------------------------------------------------------------------
__global__ void v_lse_kernel()
{
    const int gw   = blockIdx.x * 8 + (threadIdx.x >> 5);
    const int lane = threadIdx.x & 31;
    const int b    = gw >> 10;
    const float4* row = (const float4*)&g_S[(size_t)gw * NB];
    const float4* urw = (const float4*)&g_u[b * NB];

    float4 V[8];
#pragma unroll
    for (int s = 0; s < 8; ++s) {
        float4 sv = row[lane + 32 * s];
        float4 uv = urw[lane + 32 * s];
        V[s].x = sv.x + uv.x; V[s].y = sv.y + uv.y;
        V[s].z = sv.z + uv.z; V[s].w = sv.w + uv.w;
    }
    float m = -1e30f;
#pragma unroll
    for (int s = 0; s < 8; ++s)
        m = fmaxf(m, fmaxf(fmaxf(V[s].x, V[s].y), fmaxf(V[s].z, V[s].w)));
#pragma unroll
    for (int o = 16; o > 0; o >>= 1) m = fmaxf(m, __shfl_xor_sync(~0u, m, o));

    float sum = 0.f;
#pragma unroll
    for (int s = 0; s < 8; ++s)
        sum += __expf(V[s].x - m) + __expf(V[s].y - m) + __expf(V[s].z - m) + __expf(V[s].w - m);
#pragma unroll
    for (int o = 16; o > 0; o >>= 1) sum += __shfl_xor_sync(~0u, sum, o);

    if (lane == 0) g_v[gw] = -6.9314718055994531f - (m + logf(sum));
}

// ---------------------------------------------------------------------------
extern "C" void kernel_launch(void* const* d_in, const int* in_sizes, int n_in,
                              void* d_out, int out_size)
{
    const float* x    = (const float*)d_in[0];
    const float* rowe = (const float*)d_in[1];
    const float* cole = (const float*)d_in[2];
    float* out = (float*)d_out;

    cudaFuncSetAttribute(s_gemm_kernel,   cudaFuncAttributeMaxDynamicSharedMemorySize, 81920);
    cudaFuncSetAttribute(out_gemm_kernel, cudaFuncAttributeMaxDynamicSharedMemorySize, 98304);

    // 1) pos add + bf16 split, both layouts
    split_kernel<<<dim3(NB / 64, DD / 32, BB), 256>>>(x, rowe, cole);

    // 2) S = XI XI^T / sqrt(d), symmetric (36 block pairs), pipelined
    s_gemm_kernel<<<dim3(36, BB), 256, 81920>>>();

    // 3) u = -log n - rowLSE(S)
    u_lse_kernel<<<BB * NB / 8, 256>>>();

    // 4) v = -log n - colLSE(S + u)  (symmetry)
    v_lse_kernel<<<BB * NB / 8, 256>>>();

    // 5) out = XC @ exp(S+u+v)^T, exp fused into B staging, pipelined
    out_gemm_kernel<<<dim3(8, 4, BB), 256, 98304>>>(out);
}